// round 6
// baseline (speedup 1.0000x reference)
#include <cuda_runtime.h>
#include <math.h>

// Fixed problem shape
#define BB 8
#define SS 4096
#define VV 2048
#define ROWS (BB * SS)                 // 32768
#define WARPS_PER_CTA 8
#define CTA_THREADS (WARPS_PER_CTA * 32)
#define NUM_CTAS (ROWS / WARPS_PER_CTA)  // 4096
#define F4_PER_ROW (VV / 4)            // 512
#define F4_PER_LANE (F4_PER_ROW / 32)  // 16

#define DURATION_START 512
#define DURATION_END   639
#define IGNORE_INDEX  (-100)
#define MELODY_W 10.0f
#define CHORD_W   5.0f

// Per-CTA partials: x = weighted loss sum, y = valid count
__device__ float2       g_part[NUM_CTAS];
__device__ unsigned int g_ticket;   // zero-initialized; last block resets it

__device__ __forceinline__ float warp_sum(float v) {
    #pragma unroll
    for (int o = 16; o > 0; o >>= 1)
        v += __shfl_xor_sync(0xFFFFFFFFu, v, o);
    return v;
}

__device__ __forceinline__ float exp4(const float4 f) {
    return (__expf(f.x) + __expf(f.y)) + (__expf(f.z) + __expf(f.w));
}

// KEY: min-blocks=4 -> 64-register budget so the 8-deep float4 pipeline
// actually materializes in SASS (at 32 regs ptxas serialized the loads).
__global__ __launch_bounds__(CTA_THREADS, 4) void loss_kernel(
    const float* __restrict__ logits,
    const int*   __restrict__ targets,
    const int*   __restrict__ track_ids,
    const float* __restrict__ sample_weights,
    float*       __restrict__ out)
{
    const int tid  = threadIdx.x;
    const int lane = tid & 31;
    const int warp = tid >> 5;
    const int row  = blockIdx.x * WARPS_PER_CTA + warp;

    // ---- lane 0 prefetches scalar row metadata early (independent loads) ----
    int   t = 0, tr = 0;
    float tlogit = 0.0f, sw = 0.0f;
    if (lane == 0) {
        t  = targets[row];
        tr = track_ids[row];
        const int st = (t != IGNORE_INDEX) ? t : 0;
        tlogit = __ldg(&logits[(size_t)row * VV + st]);
        sw = __ldg(&sample_weights[row / SS]);
    }

    // ---- single streaming pass, software-pipelined: 8 float4 in flight ----
    const float4* rp = reinterpret_cast<const float4*>(logits)
                       + (size_t)row * F4_PER_ROW + lane;

    float4 c0 = __ldcs(rp +  0 * 32);
    float4 c1 = __ldcs(rp +  1 * 32);
    float4 c2 = __ldcs(rp +  2 * 32);
    float4 c3 = __ldcs(rp +  3 * 32);

    float s0 = 0.0f, s1 = 0.0f, s2 = 0.0f, s3 = 0.0f;

    #pragma unroll
    for (int g = 0; g < 4; g++) {
        float4 n0, n1, n2, n3;
        if (g < 3) {
            n0 = __ldcs(rp + (4 * g + 4) * 32);
            n1 = __ldcs(rp + (4 * g + 5) * 32);
            n2 = __ldcs(rp + (4 * g + 6) * 32);
            n3 = __ldcs(rp + (4 * g + 7) * 32);
        }
        s0 += exp4(c0);
        s1 += exp4(c1);
        s2 += exp4(c2);
        s3 += exp4(c3);
        if (g < 3) { c0 = n0; c1 = n1; c2 = n2; c3 = n3; }
    }
    float s = warp_sum((s0 + s1) + (s2 + s3));

    __shared__ float2 s_part[WARPS_PER_CTA];
    if (lane == 0) {
        const bool valid = (t != IGNORE_INDEX);
        const float nll = __logf(s) - tlogit;

        const bool shortv = (t >= DURATION_START) && (t <= DURATION_END) &&
                            ((t - DURATION_START) < 3);
        float w = 1.0f;
        if (shortv) w = (tr == 0) ? MELODY_W : (tr == 1) ? CHORD_W : 1.0f;

        s_part[warp] = make_float2(valid ? nll * w * sw : 0.0f,
                                   valid ? 1.0f : 0.0f);
    }
    __syncthreads();

    __shared__ bool s_is_last;
    if (tid == 0) {
        float ls = 0.0f, cs = 0.0f;
        #pragma unroll
        for (int w = 0; w < WARPS_PER_CTA; w++) { ls += s_part[w].x; cs += s_part[w].y; }
        g_part[blockIdx.x] = make_float2(ls, cs);
        __threadfence();
        const unsigned tk = atomicAdd(&g_ticket, 1u);
        s_is_last = (tk == (unsigned)(gridDim.x - 1));
    }
    __syncthreads();

    // ---- last CTA performs the deterministic final reduction ----
    if (s_is_last) {
        float ls = 0.0f, cs = 0.0f;
        for (int i = tid; i < NUM_CTAS; i += CTA_THREADS) {
            const float2 p = __ldcg(&g_part[i]);   // bypass L1 (written by other SMs)
            ls += p.x; cs += p.y;
        }
        ls = warp_sum(ls);
        cs = warp_sum(cs);
        __shared__ float sl[WARPS_PER_CTA], sc[WARPS_PER_CTA];
        if (lane == 0) { sl[warp] = ls; sc[warp] = cs; }
        __syncthreads();
        if (tid == 0) {
            float L = 0.0f, C = 0.0f;
            #pragma unroll
            for (int w = 0; w < WARPS_PER_CTA; w++) { L += sl[w]; C += sc[w]; }
            out[0] = L / fmaxf(C, 1.0f);
            g_ticket = 0;   // reset for next graph replay
        }
    }
}

extern "C" void kernel_launch(void* const* d_in, const int* in_sizes, int n_in,
                              void* d_out, int out_size)
{
    const float* logits         = (const float*)d_in[0];
    const int*   targets        = (const int*)  d_in[1];
    const int*   track_ids      = (const int*)  d_in[2];
    const float* sample_weights = (const float*)d_in[3];
    float* out = (float*)d_out;

    loss_kernel<<<NUM_CTAS, CTA_THREADS>>>(logits, targets, track_ids,
                                           sample_weights, out);
}